// round 2
// baseline (speedup 1.0000x reference)
#include <cuda_runtime.h>

// Problem constants
#define NSEQ    4
#define BATCH   128
#define HID     1024
#define EMB     512
#define SEQLEN  256
#define CHUNK   32                 // hidden columns per CTA
#define NCHUNK  (HID / CHUNK)      // 32
#define NCTA    (NSEQ * NCHUNK)    // 128 CTAs -> all co-resident on 148 SMs
#define KC      32                 // K-tile
#define NKC     (HID / KC)         // 32
#define THREADS 256

// Persistent device state (no cudaMalloc allowed)
__device__ float g_X[NSEQ * BATCH * HID];       // x_spin per sequence (step-0 input)
__device__ float g_S[2 * NSEQ * BATCH * HID];   // double-buffered recurrent state
__device__ unsigned g_bar_cnt;
__device__ unsigned g_bar_gen;

__device__ __forceinline__ void fma2(unsigned long long &acc,
                                     unsigned long long a,
                                     unsigned long long b) {
    asm("fma.rn.f32x2 %0, %1, %2, %0;" : "+l"(acc) : "l"(a), "l"(b));
}
__device__ __forceinline__ unsigned long long pack2(float x) {
    unsigned u = __float_as_uint(x);
    unsigned long long r;
    asm("mov.b64 %0, {%1, %1};" : "=l"(r) : "r"(u));
    return r;
}
__device__ __forceinline__ float lo2(unsigned long long v) {
    return __uint_as_float((unsigned)(v & 0xffffffffull));
}
__device__ __forceinline__ float hi2(unsigned long long v) {
    return __uint_as_float((unsigned)(v >> 32));
}

// Sense-reversing grid barrier. Safe: all NCTA=128 CTAs are co-resident
// (1 CTA/SM worst case, 128 <= 148 SMs).
__device__ __forceinline__ void grid_barrier() {
    __syncthreads();
    if (threadIdx.x == 0) {
        unsigned gen = *((volatile unsigned *)&g_bar_gen);
        __threadfence();
        unsigned my = atomicAdd(&g_bar_cnt, 1);
        if (my == NCTA - 1) {
            atomicExch(&g_bar_cnt, 0);
            __threadfence();
            atomicAdd(&g_bar_gen, 1);
        } else {
            while (*((volatile unsigned *)&g_bar_gen) == gen) { }
        }
        __threadfence();
    }
    __syncthreads();
}

__device__ __forceinline__ float sigmoidf_(float x) {
    return 1.0f / (1.0f + __expf(-x));
}

__global__ __launch_bounds__(THREADS, 1)
void gru_persistent_kernel(const float *__restrict__ x,
                           const float *__restrict__ Wih_up,
                           const float *__restrict__ Whh_up,
                           const float *__restrict__ Wih_dn,
                           const float *__restrict__ Whh_dn,
                           const float *__restrict__ bih_up,
                           const float *__restrict__ bhh_up,
                           const float *__restrict__ bih_dn,
                           const float *__restrict__ bhh_dn,
                           float *__restrict__ out) {
    // A tile transposed: As[k][m], stride 130 (even -> 8B-aligned pair loads,
    // only 2-way write conflict). B tile: Bs[n][k], stride 33 (conflict-free).
    __shared__ __align__(16) float As[KC][BATCH + 2];
    __shared__ __align__(16) float Bs[6 * CHUNK][KC + 1];

    const int tid = threadIdx.x;
    const int j   = tid & 31;     // hidden-col lane within chunk
    const int mg  = tid >> 5;     // warp id -> 16-row batch group
    const int m0  = mg * 16;

    const int s    = blockIdx.x >> 5;   // sequence: 0=up_su 1=up_sd 2=dn_su 3=dn_sd
    const int chnk = blockIdx.x & 31;
    const int c0   = chnk * CHUNK;
    const int wset = s >> 1;            // 0=up weights, 1=down weights
    const int spin = s & 1;             // 0: [x,x]  1: [x,-x]
    const int jg   = c0 + j;            // global hidden column

    const float *Wih = wset ? Wih_dn : Wih_up;
    const float *Whh = wset ? Whh_dn : Whh_up;
    const float *bih = wset ? bih_dn : bih_up;
    const float *bhh = wset ? bhh_dn : bhh_up;

    // ---- init: build x_spin into g_X[s] for our 32 columns ----
    {
        float *X = g_X + s * BATCH * HID;
#pragma unroll
        for (int i = 0; i < 16; i++) {
            int e  = tid + i * 256;     // 0..4095 over 128 rows x 32 cols
            int m  = e >> 5;
            int jj = e & 31;
            int col = c0 + jj;
            float v;
            if (col < EMB) v = x[m * EMB + col];
            else { v = x[m * EMB + (col - EMB)]; if (spin) v = -v; }
            X[m * HID + col] = v;
        }
    }
    grid_barrier();

    // recurrent state for our (16 rows x 1 col) per thread, kept in registers
    float h[16];
#pragma unroll
    for (int i = 0; i < 16; i++) h[i] = 0.0f;

    const float bi_r = bih[jg], bi_z = bih[HID + jg], bi_n = bih[2 * HID + jg];
    const float bh_r = bhh[jg], bh_z = bhh[HID + jg], bh_n = bhh[2 * HID + jg];

    for (int t = 0; t < SEQLEN; ++t) {
        // t==0: input is x_spin and h==0 (gh groups stay zero -> gh = bhh).
        // t>=1: input == h, one shared A tile feeds all 6 gate groups.
        const float *A = (t == 0) ? (g_X + s * BATCH * HID)
                                  : (g_S + ((t & 1) * NSEQ + s) * BATCH * HID);
        float *Sw = g_S + (((t + 1) & 1) * NSEQ + s) * BATCH * HID;

        // 6 gate groups (Wih r,z,n ; Whh r,z,n) x 8 packed row-pairs
        unsigned long long acc[6][8];
#pragma unroll
        for (int g = 0; g < 6; g++)
#pragma unroll
            for (int p = 0; p < 8; p++) acc[g][p] = 0ull;

        for (int kc = 0; kc < NKC; ++kc) {
            const int kb = kc * KC;
            // A tile (transpose on store)
#pragma unroll
            for (int i = 0; i < 16; i++) {
                int e = tid + i * 256; int m = e >> 5; int kk = e & 31;
                As[kk][m] = A[m * HID + kb + kk];
            }
            // B tile: 6 gate groups x 32 cols of weight rows
#pragma unroll
            for (int i = 0; i < 24; i++) {
                int e = tid + i * 256; int n = e >> 5; int kk = e & 31;
                int g = n >> 5; int jj = n & 31;
                const float *W = (g < 3) ? Wih : Whh;
                int grow = (g < 3 ? g : g - 3) * HID + c0 + jj;
                Bs[n][kk] = W[grow * HID + kb + kk];
            }
            __syncthreads();

            if (t == 0) {
#pragma unroll 4
                for (int kk = 0; kk < KC; ++kk) {
                    unsigned long long b0 = pack2(Bs[0 * 32 + j][kk]);
                    unsigned long long b1 = pack2(Bs[1 * 32 + j][kk]);
                    unsigned long long b2 = pack2(Bs[2 * 32 + j][kk]);
#pragma unroll
                    for (int p = 0; p < 8; p++) {
                        unsigned long long a2 =
                            *reinterpret_cast<const unsigned long long *>(&As[kk][m0 + 2 * p]);
                        fma2(acc[0][p], a2, b0);
                        fma2(acc[1][p], a2, b1);
                        fma2(acc[2][p], a2, b2);
                    }
                }
            } else {
#pragma unroll 2
                for (int kk = 0; kk < KC; ++kk) {
                    unsigned long long b0 = pack2(Bs[0 * 32 + j][kk]);
                    unsigned long long b1 = pack2(Bs[1 * 32 + j][kk]);
                    unsigned long long b2 = pack2(Bs[2 * 32 + j][kk]);
                    unsigned long long b3 = pack2(Bs[3 * 32 + j][kk]);
                    unsigned long long b4 = pack2(Bs[4 * 32 + j][kk]);
                    unsigned long long b5 = pack2(Bs[5 * 32 + j][kk]);
#pragma unroll
                    for (int p = 0; p < 8; p++) {
                        unsigned long long a2 =
                            *reinterpret_cast<const unsigned long long *>(&As[kk][m0 + 2 * p]);
                        fma2(acc[0][p], a2, b0);
                        fma2(acc[1][p], a2, b1);
                        fma2(acc[2][p], a2, b2);
                        fma2(acc[3][p], a2, b3);
                        fma2(acc[4][p], a2, b4);
                        fma2(acc[5][p], a2, b5);
                    }
                }
            }
            __syncthreads();
        }

        // ---- epilogue: fused GRU gate math, fully thread-local ----
#pragma unroll
        for (int p = 0; p < 8; p++) {
#pragma unroll
            for (int half = 0; half < 2; ++half) {
                int mi = 2 * p + half;
                int m  = m0 + mi;
                float a0 = half ? hi2(acc[0][p]) : lo2(acc[0][p]);
                float a1 = half ? hi2(acc[1][p]) : lo2(acc[1][p]);
                float a2v = half ? hi2(acc[2][p]) : lo2(acc[2][p]);
                float a3 = half ? hi2(acc[3][p]) : lo2(acc[3][p]);
                float a4 = half ? hi2(acc[4][p]) : lo2(acc[4][p]);
                float a5 = half ? hi2(acc[5][p]) : lo2(acc[5][p]);
                float r = sigmoidf_(a0 + bi_r + a3 + bh_r);
                float z = sigmoidf_(a1 + bi_z + a4 + bh_z);
                float n = tanhf(a2v + bi_n + r * (a5 + bh_n));
                float hn = (1.0f - z) * n + z * h[mi];
                h[mi] = hn;
                out[((s * BATCH + m) * SEQLEN + t) * HID + jg] = hn;  // [s][b][t][h]
                Sw[m * HID + jg] = hn;                                 // next-step state
            }
        }
        // One barrier per step: writes go to the other state buffer, so
        // read-before-overwrite hazards cannot occur.
        grid_barrier();
    }
}

extern "C" void kernel_launch(void *const *d_in, const int *in_sizes, int n_in,
                              void *d_out, int out_size) {
    const float *x      = (const float *)d_in[0];
    const float *Wih_up = (const float *)d_in[1];
    const float *Whh_up = (const float *)d_in[2];
    const float *Wih_dn = (const float *)d_in[3];
    const float *Whh_dn = (const float *)d_in[4];
    const float *bih_up = (const float *)d_in[5];
    const float *bhh_up = (const float *)d_in[6];
    const float *bih_dn = (const float *)d_in[7];
    const float *bhh_dn = (const float *)d_in[8];
    float *out = (float *)d_out;

    gru_persistent_kernel<<<NCTA, THREADS>>>(x, Wih_up, Whh_up, Wih_dn, Whh_dn,
                                             bih_up, bhh_up, bih_dn, bhh_dn, out);
}

// round 4
// speedup vs baseline: 3.2584x; 3.2584x over previous
#include <cuda_runtime.h>
#include <cuda_bf16.h>
#include <cstdint>

// ---------------- problem constants ----------------
#define NSEQ    4
#define BATCH   128
#define HID     1024
#define EMB     512
#define SEQLEN  256
#define NCTA    128
#define THREADS 256
#define KCH     64                 // K columns per streamed chunk
#define NKCH    16                 // chunks per step (K=1024)

#define IMG_AH  16384              // 128 rows x 128B (64 bf16), SW128-swizzled
#define IMG_BH  24576              // 192 rows x 128B
#define BLOB_A  (2*IMG_AH)         // [Ah | Al] = 32KB
#define BLOB_B  (2*IMG_BH)         // [Bh | Bl] = 48KB
#define STAGE   (BLOB_A + BLOB_B)  // 80KB
#define NSTAGE  2
#define DYNSMEM (NSTAGE*STAGE + 1024)

// ---------------- persistent device buffers ----------------
__device__ __align__(16) unsigned char g_Wb[(size_t)2*32*16*BLOB_B]; // 48MB swizzled weights
__device__ __align__(16) unsigned char g_A0[(size_t)4*16*BLOB_A];    // x_spin images
__device__ __align__(16) unsigned char g_St[(size_t)2*4*16*BLOB_A];  // double-buffered h images
__device__ unsigned g_bar_cnt;
__device__ unsigned g_bar_gen;

// ---------------- PTX helpers ----------------
__device__ __forceinline__ uint32_t smem_u32(const void* p) {
    uint32_t a;
    asm("{ .reg .u64 t; cvta.to.shared.u64 t, %1; cvt.u32.u64 %0, t; }" : "=r"(a) : "l"(p));
    return a;
}
__device__ __forceinline__ void mbar_init(uint32_t m, uint32_t cnt) {
    asm volatile("mbarrier.init.shared.b64 [%0], %1;" :: "r"(m), "r"(cnt) : "memory");
}
__device__ __forceinline__ void mbar_expect_tx(uint32_t m, uint32_t bytes) {
    asm volatile("mbarrier.arrive.expect_tx.shared.b64 _, [%0], %1;" :: "r"(m), "r"(bytes) : "memory");
}
__device__ __forceinline__ void mbar_arrive(uint32_t m) {
    asm volatile("mbarrier.arrive.shared.b64 _, [%0];" :: "r"(m) : "memory");
}
__device__ __forceinline__ void mbar_wait(uint32_t m, uint32_t parity) {
    asm volatile(
        "{\n\t.reg .pred P;\n\t"
        "W_%=:\n\t"
        "mbarrier.try_wait.parity.shared::cta.b64 P, [%0], %1, 0x989680;\n\t"
        "@P bra.uni D_%=;\n\t"
        "bra.uni W_%=;\n\t"
        "D_%=:\n\t}"
        :: "r"(m), "r"(parity) : "memory");
}
__device__ __forceinline__ void bulk_copy(uint32_t dst, const void* src, uint32_t bytes, uint32_t m) {
    asm volatile(
        "cp.async.bulk.shared::cluster.global.mbarrier::complete_tx::bytes [%0], [%1], %2, [%3];"
        :: "r"(dst), "l"(src), "r"(bytes), "r"(m) : "memory");
}
__device__ __forceinline__ void ldsm4(uint32_t* r, uint32_t a) {
    asm volatile("ldmatrix.sync.aligned.m8n8.x4.shared.b16 {%0,%1,%2,%3}, [%4];"
                 : "=r"(r[0]), "=r"(r[1]), "=r"(r[2]), "=r"(r[3]) : "r"(a));
}
__device__ __forceinline__ void ldsm2(uint32_t* r, uint32_t a) {
    asm volatile("ldmatrix.sync.aligned.m8n8.x2.shared.b16 {%0,%1}, [%2];"
                 : "=r"(r[0]), "=r"(r[1]) : "r"(a));
}
__device__ __forceinline__ void mma16816(float* d, const uint32_t* a, const uint32_t* b) {
    asm("mma.sync.aligned.m16n8k16.row.col.f32.bf16.bf16.f32 "
        "{%0,%1,%2,%3}, {%4,%5,%6,%7}, {%8,%9}, {%0,%1,%2,%3};"
        : "+f"(d[0]), "+f"(d[1]), "+f"(d[2]), "+f"(d[3])
        : "r"(a[0]), "r"(a[1]), "r"(a[2]), "r"(a[3]), "r"(b[0]), "r"(b[1]));
}

__device__ __forceinline__ void grid_barrier() {
    __threadfence();
    __syncthreads();
    if (threadIdx.x == 0) {
        asm volatile("fence.proxy.async.global;" ::: "memory");
        unsigned gen = *((volatile unsigned *)&g_bar_gen);
        __threadfence();
        unsigned my = atomicAdd(&g_bar_cnt, 1);
        if (my == NCTA - 1) {
            atomicExch(&g_bar_cnt, 0);
            __threadfence();
            atomicAdd(&g_bar_gen, 1);
        } else {
            while (*((volatile unsigned *)&g_bar_gen) == gen) { }
        }
        __threadfence();
        asm volatile("fence.proxy.async.global;" ::: "memory");
    }
    __syncthreads();
}

__device__ __forceinline__ float sigm(float x) { return 1.0f / (1.0f + __expf(-x)); }
__device__ __forceinline__ unsigned short us16(__nv_bfloat16 v) {
    return reinterpret_cast<unsigned short&>(v);
}
__device__ __forceinline__ uint32_t sw128(uint32_t off) { return off ^ ((off >> 3) & 0x70); }

// ---------------- prologue: weights -> swizzled bf16 hi/lo images ----------------
__global__ void prep_weights(const float* __restrict__ Wih_up, const float* __restrict__ Whh_up,
                             const float* __restrict__ Wih_dn, const float* __restrict__ Whh_dn) {
    int b = blockIdx.x;                 // 0..1023
    int set   = b >> 9;
    int chunk = (b >> 4) & 31;
    int kc    = b & 15;
    const float* Wih = set ? Wih_dn : Wih_up;
    const float* Whh = set ? Whh_dn : Whh_up;
    unsigned char* img = g_Wb + ((size_t)((set * 32 + chunk) * 16 + kc)) * BLOB_B;
    for (int e = threadIdx.x; e < 192 * 64; e += blockDim.x) {
        int n = e >> 6, col = e & 63;
        int g = n >> 5, jj = n & 31;
        const float* W = (g < 3) ? Wih : Whh;
        int gg = (g < 3) ? g : (g - 3);
        float v = W[(size_t)(gg * HID + chunk * 32 + jj) * HID + kc * 64 + col];
        __nv_bfloat16 hi = __float2bfloat16(v);
        __nv_bfloat16 lo = __float2bfloat16(v - __bfloat162float(hi));
        uint32_t sw = sw128((uint32_t)(n * 128 + col * 2));
        *(__nv_bfloat16*)(img + sw)          = hi;
        *(__nv_bfloat16*)(img + IMG_BH + sw) = lo;
    }
}

// ---------------- prologue: x_spin -> step-0 A images ----------------
__global__ void prep_x(const float* __restrict__ x) {
    int b = blockIdx.x;                 // 0..63 = s*16 + kc
    int s = b >> 4, kc = b & 15;
    unsigned char* img = g_A0 + (size_t)(s * 16 + kc) * BLOB_A;
    for (int e = threadIdx.x; e < 128 * 64; e += blockDim.x) {
        int m = e >> 6, col = e & 63;
        int gc = kc * 64 + col;
        float v = x[m * EMB + (gc & (EMB - 1))];
        if ((s & 1) && gc >= EMB) v = -v;
        __nv_bfloat16 hi = __float2bfloat16(v);
        __nv_bfloat16 lo = __float2bfloat16(v - __bfloat162float(hi));
        uint32_t sw = sw128((uint32_t)(m * 128 + col * 2));
        *(__nv_bfloat16*)(img + sw)          = hi;
        *(__nv_bfloat16*)(img + IMG_AH + sw) = lo;
    }
}

// ---------------- persistent HMMA GRU kernel ----------------
__global__ __launch_bounds__(THREADS, 1)
void gru_mma_kernel(const float* __restrict__ bih_up, const float* __restrict__ bhh_up,
                    const float* __restrict__ bih_dn, const float* __restrict__ bhh_dn,
                    float* __restrict__ out) {
    extern __shared__ __align__(16) unsigned char dynsmem[];
    __shared__ __align__(8) unsigned long long s_mbar[4];   // full0 full1 emp0 emp1

    const int tid  = threadIdx.x;
    const int lane = tid & 31;
    const int wid  = tid >> 5;
    const int wm   = wid >> 2;         // 0..1  (M half)
    const int wn   = wid & 3;          // 0..3  (j-oct)

    const int s     = blockIdx.x >> 5;
    const int chunk = blockIdx.x & 31;
    const int wset  = s >> 1;
    const int c0    = chunk * 32;

    const float* bih = wset ? bih_dn : bih_up;
    const float* bhh = wset ? bhh_dn : bhh_up;

    // this thread's two hidden columns
    const int j0  = wn * 8 + 2 * (lane & 3);
    const int jg  = c0 + j0;
    const float bR0 = bih[jg]     + bhh[jg];
    const float bR1 = bih[jg + 1] + bhh[jg + 1];
    const float bZ0 = bih[HID + jg]     + bhh[HID + jg];
    const float bZ1 = bih[HID + jg + 1] + bhh[HID + jg + 1];
    const float bI0 = bih[2 * HID + jg],     bI1 = bih[2 * HID + jg + 1];
    const float bH0 = bhh[2 * HID + jg],     bH1 = bhh[2 * HID + jg + 1];

    const uint32_t mb = smem_u32(s_mbar);
    const uint32_t mb_full[2] = { mb, mb + 8 };
    const uint32_t mb_emp[2]  = { mb + 16, mb + 24 };
    if (tid == 0) {
        mbar_init(mb_full[0], 1); mbar_init(mb_full[1], 1);
        mbar_init(mb_emp[0], THREADS); mbar_init(mb_emp[1], THREADS);
    }
    __syncthreads();

    const uint32_t sm0 = (smem_u32(dynsmem) + 1023u) & ~1023u;

    // ldmatrix address components (swizzle folded: kbytes stays in bits 0-6)
    const int rowA  = wm * 64 + (lane & 15);
    const uint32_t axor = (uint32_t)((rowA & 7) << 4);
    const uint32_t aklane = (uint32_t)((lane >> 4) * 16);
    uint32_t arow[4];
#pragma unroll
    for (int mt = 0; mt < 4; mt++) arow[mt] = (uint32_t)((rowA + mt * 16) * 128);

    const int rowB  = wn * 8 + (lane & 7);
    const uint32_t bxor = (uint32_t)((rowB & 7) << 4);
    const uint32_t bklane = (uint32_t)(((lane >> 3) & 1) * 16);
    uint32_t brow[6];
#pragma unroll
    for (int g = 0; g < 6; g++) brow[g] = (uint32_t)((rowB + g * 32) * 128);

    const unsigned char* Wblob = g_Wb + (size_t)(wset * 32 + chunk) * 16 * BLOB_B;

    float h[16];
#pragma unroll
    for (int i = 0; i < 16; i++) h[i] = 0.0f;

    for (int t = 0; t < SEQLEN; ++t) {
        const unsigned char* Ab = (t == 0)
            ? (g_A0 + (size_t)s * 16 * BLOB_A)
            : (g_St + (size_t)((t & 1) * 4 + s) * 16 * BLOB_A);

        // prefetch first two chunks
        if (tid == 0) {
#pragma unroll
            for (int i = 0; i < NSTAGE; i++) {
                int q = t * NKCH + i;
                int st = q & 1;
                if (q >= 2) mbar_wait(mb_emp[st], ((q - 2) >> 1) & 1);
                mbar_expect_tx(mb_full[st], STAGE);
                uint32_t sb = sm0 + (uint32_t)st * STAGE;
                bulk_copy(sb,          Ab    + (size_t)i * BLOB_A, BLOB_A, mb_full[st]);
                bulk_copy(sb + BLOB_A, Wblob + (size_t)i * BLOB_B, BLOB_B, mb_full[st]);
            }
        }

        float acc[4][6][4];
#pragma unroll
        for (int mt = 0; mt < 4; mt++)
#pragma unroll
            for (int g = 0; g < 6; g++)
#pragma unroll
                for (int r = 0; r < 4; r++) acc[mt][g][r] = 0.0f;

        for (int kc = 0; kc < NKCH; ++kc) {
            const int q = t * NKCH + kc;
            const int st = q & 1;
            mbar_wait(mb_full[st], (q >> 1) & 1);
            const uint32_t sb  = sm0 + (uint32_t)st * STAGE;
            const uint32_t sAh = sb;
            const uint32_t sAl = sb + IMG_AH;
            const uint32_t sBh = sb + BLOB_A;
            const uint32_t sBl = sb + BLOB_A + IMG_BH;

            for (int kk = 0; kk < 4; ++kk) {
                const uint32_t ak = ((uint32_t)(kk * 32) + aklane) ^ axor;
                const uint32_t bk = ((uint32_t)(kk * 32) + bklane) ^ bxor;
                uint32_t ah[4][4], al[4][4], bh[6][2], bl[6][2];
#pragma unroll
                for (int mt = 0; mt < 4; mt++) {
                    ldsm4(ah[mt], sAh + arow[mt] + ak);
                    ldsm4(al[mt], sAl + arow[mt] + ak);
                }
#pragma unroll
                for (int g = 0; g < 6; g++) {
                    ldsm2(bh[g], sBh + brow[g] + bk);
                    ldsm2(bl[g], sBl + brow[g] + bk);
                }
#pragma unroll
                for (int g = 0; g < 6; g++)
#pragma unroll
                    for (int mt = 0; mt < 4; mt++) {
                        mma16816(acc[mt][g], ah[mt], bh[g]);
                        mma16816(acc[mt][g], ah[mt], bl[g]);
                        mma16816(acc[mt][g], al[mt], bh[g]);
                    }
            }
            mbar_arrive(mb_emp[st]);

            // prefetch chunk kc+2 (same step only; next step's A isn't ready)
            if (tid == 0 && kc + NSTAGE < NKCH) {
                int q2 = q + NSTAGE;
                int st2 = q2 & 1;
                mbar_wait(mb_emp[st2], ((q2 - 2) >> 1) & 1);
                mbar_expect_tx(mb_full[st2], STAGE);
                uint32_t sb2 = sm0 + (uint32_t)st2 * STAGE;
                bulk_copy(sb2,          Ab    + (size_t)(kc + NSTAGE) * BLOB_A, BLOB_A, mb_full[st2]);
                bulk_copy(sb2 + BLOB_A, Wblob + (size_t)(kc + NSTAGE) * BLOB_B, BLOB_B, mb_full[st2]);
            }
        }

        // ---------------- epilogue: lane-local gate fusion ----------------
        unsigned char* Sbase = g_St + ((size_t)(((t + 1) & 1) * 4 + s) * 16 + (chunk >> 1)) * BLOB_A;
        const uint32_t colbyte = (uint32_t)(((chunk & 1) * 32 + j0) * 2);

#pragma unroll
        for (int mt = 0; mt < 4; mt++) {
#pragma unroll
            for (int rr = 0; rr < 2; rr++) {
                const int ri = rr * 2;
                const int m  = wm * 64 + mt * 16 + rr * 8 + (lane >> 2);
                float hr0 = 0.f, hz0 = 0.f, hn0 = 0.f, hr1 = 0.f, hz1 = 0.f, hn1 = 0.f;
                if (t) {
                    hr0 = acc[mt][3][ri];     hr1 = acc[mt][3][ri + 1];
                    hz0 = acc[mt][4][ri];     hz1 = acc[mt][4][ri + 1];
                    hn0 = acc[mt][5][ri];     hn1 = acc[mt][5][ri + 1];
                }
                float r0 = sigm(acc[mt][0][ri]     + hr0 + bR0);
                float r1 = sigm(acc[mt][0][ri + 1] + hr1 + bR1);
                float z0 = sigm(acc[mt][1][ri]     + hz0 + bZ0);
                float z1 = sigm(acc[mt][1][ri + 1] + hz1 + bZ1);
                float n0 = tanhf(acc[mt][2][ri]     + bI0 + r0 * (hn0 + bH0));
                float n1 = tanhf(acc[mt][2][ri + 1] + bI1 + r1 * (hn1 + bH1));
                const int idx = mt * 4 + rr * 2;
                float v0 = (1.0f - z0) * n0 + z0 * h[idx];
                float v1 = (1.0f - z1) * n1 + z1 * h[idx + 1];
                h[idx] = v0; h[idx + 1] = v1;

                // output
                *reinterpret_cast<float2*>(
                    out + ((size_t)(s * BATCH + m) * SEQLEN + t) * HID + jg) = make_float2(v0, v1);

                // next-step state image (bf16 hi/lo, swizzled)
                __nv_bfloat16 h0 = __float2bfloat16(v0);
                __nv_bfloat16 h1 = __float2bfloat16(v1);
                uint32_t hip = (uint32_t)us16(h0) | ((uint32_t)us16(h1) << 16);
                __nv_bfloat16 l0 = __float2bfloat16(v0 - __bfloat162float(h0));
                __nv_bfloat16 l1 = __float2bfloat16(v1 - __bfloat162float(h1));
                uint32_t lop = (uint32_t)us16(l0) | ((uint32_t)us16(l1) << 16);
                uint32_t sw = sw128((uint32_t)(m * 128) + colbyte);
                *reinterpret_cast<uint32_t*>(Sbase + sw)          = hip;
                *reinterpret_cast<uint32_t*>(Sbase + IMG_AH + sw) = lop;
            }
        }
        grid_barrier();
    }
}

extern "C" void kernel_launch(void* const* d_in, const int* in_sizes, int n_in,
                              void* d_out, int out_size) {
    const float* x      = (const float*)d_in[0];
    const float* Wih_up = (const float*)d_in[1];
    const float* Whh_up = (const float*)d_in[2];
    const float* Wih_dn = (const float*)d_in[3];
    const float* Whh_dn = (const float*)d_in[4];
    const float* bih_up = (const float*)d_in[5];
    const float* bhh_up = (const float*)d_in[6];
    const float* bih_dn = (const float*)d_in[7];
    const float* bhh_dn = (const float*)d_in[8];
    float* out = (float*)d_out;

    cudaFuncSetAttribute(gru_mma_kernel, cudaFuncAttributeMaxDynamicSharedMemorySize, DYNSMEM);

    prep_weights<<<1024, 256>>>(Wih_up, Whh_up, Wih_dn, Whh_dn);
    prep_x<<<64, 256>>>(x);
    gru_mma_kernel<<<NCTA, THREADS, DYNSMEM>>>(bih_up, bhh_up, bih_dn, bhh_dn, out);
}

// round 5
// speedup vs baseline: 4.4780x; 1.3743x over previous
#include <cuda_runtime.h>
#include <cuda_fp16.h>
#include <cstdint>

// ---------------- problem constants ----------------
#define NSEQ    4
#define BATCH   128
#define HID     1024
#define EMB     512
#define SEQLEN  256
#define NCTA    128
#define THREADS 256
#define NKCH    16                 // K chunks of 64 per step

#define IMG_A   16384              // 128 rows x 128B (64 fp16), SW128-swizzled
#define BLOB_A  (2*IMG_A)          // [Ah | Al] = 32KB
#define IMG_B   24576              // 192 rows x 128B
#define BLOB_B  IMG_B              // B hi only = 24KB
#define STAGE   (BLOB_A + BLOB_B)  // 56KB
#define NSTAGE  3
#define DYNSMEM (NSTAGE*STAGE + 1024)

// ---------------- persistent device buffers ----------------
__device__ __align__(16) unsigned char g_Wb[(size_t)2*32*16*BLOB_B]; // 25MB fp16 weights (swizzled)
__device__ __align__(16) unsigned char g_A0[(size_t)4*16*BLOB_A];    // x_spin images
__device__ __align__(16) unsigned char g_St[(size_t)2*4*16*BLOB_A];  // double-buffered h images
__device__ unsigned g_bar_cnt;
__device__ unsigned g_bar_gen;

// ---------------- PTX helpers ----------------
__device__ __forceinline__ uint32_t smem_u32(const void* p) {
    uint32_t a;
    asm("{ .reg .u64 t; cvta.to.shared.u64 t, %1; cvt.u32.u64 %0, t; }" : "=r"(a) : "l"(p));
    return a;
}
__device__ __forceinline__ void mbar_init(uint32_t m, uint32_t cnt) {
    asm volatile("mbarrier.init.shared.b64 [%0], %1;" :: "r"(m), "r"(cnt) : "memory");
}
__device__ __forceinline__ void mbar_arrive_expect_tx(uint32_t m, uint32_t bytes) {
    asm volatile("mbarrier.arrive.expect_tx.shared.b64 _, [%0], %1;" :: "r"(m), "r"(bytes) : "memory");
}
__device__ __forceinline__ void mbar_arrive(uint32_t m) {
    asm volatile("mbarrier.arrive.shared.b64 _, [%0];" :: "r"(m) : "memory");
}
__device__ __forceinline__ void mbar_wait(uint32_t m, uint32_t parity) {
    asm volatile(
        "{\n\t.reg .pred P;\n\t"
        "W_%=:\n\t"
        "mbarrier.try_wait.parity.shared::cta.b64 P, [%0], %1, 0x989680;\n\t"
        "@P bra.uni D_%=;\n\t"
        "bra.uni W_%=;\n\t"
        "D_%=:\n\t}"
        :: "r"(m), "r"(parity) : "memory");
}
__device__ __forceinline__ void bulk_copy(uint32_t dst, const void* src, uint32_t bytes, uint32_t m) {
    asm volatile(
        "cp.async.bulk.shared::cluster.global.mbarrier::complete_tx::bytes [%0], [%1], %2, [%3];"
        :: "r"(dst), "l"(src), "r"(bytes), "r"(m) : "memory");
}
__device__ __forceinline__ void ldsm4(uint32_t* r, uint32_t a) {
    asm volatile("ldmatrix.sync.aligned.m8n8.x4.shared.b16 {%0,%1,%2,%3}, [%4];"
                 : "=r"(r[0]), "=r"(r[1]), "=r"(r[2]), "=r"(r[3]) : "r"(a));
}
__device__ __forceinline__ void mma16816(float* d, const uint32_t* a, const uint32_t* b) {
    asm("mma.sync.aligned.m16n8k16.row.col.f32.f16.f16.f32 "
        "{%0,%1,%2,%3}, {%4,%5,%6,%7}, {%8,%9}, {%0,%1,%2,%3};"
        : "+f"(d[0]), "+f"(d[1]), "+f"(d[2]), "+f"(d[3])
        : "r"(a[0]), "r"(a[1]), "r"(a[2]), "r"(a[3]), "r"(b[0]), "r"(b[1]));
}

__device__ __forceinline__ void grid_barrier() {
    __threadfence();
    __syncthreads();
    if (threadIdx.x == 0) {
        asm volatile("fence.proxy.async.global;" ::: "memory");
        unsigned gen = *((volatile unsigned *)&g_bar_gen);
        __threadfence();
        unsigned my = atomicAdd(&g_bar_cnt, 1);
        if (my == NCTA - 1) {
            atomicExch(&g_bar_cnt, 0);
            __threadfence();
            atomicAdd(&g_bar_gen, 1);
        } else {
            while (*((volatile unsigned *)&g_bar_gen) == gen) { }
        }
        __threadfence();
        asm volatile("fence.proxy.async.global;" ::: "memory");
    }
    __syncthreads();
}

__device__ __forceinline__ float sigm(float x) { return 1.0f / (1.0f + __expf(-x)); }
__device__ __forceinline__ unsigned short us16(__half v) {
    return reinterpret_cast<unsigned short&>(v);
}
__device__ __forceinline__ uint32_t sw128(uint32_t off) { return off ^ ((off >> 3) & 0x70); }

// ---------------- fused prologue: weights (fp16 hi) + x images (fp16 hi/lo) ----
__global__ void prep_all(const float* __restrict__ Wih_up, const float* __restrict__ Whh_up,
                         const float* __restrict__ Wih_dn, const float* __restrict__ Whh_dn,
                         const float* __restrict__ x) {
    int b = blockIdx.x;
    if (b < 1024) {
        int set   = b >> 9;
        int chunk = (b >> 4) & 31;
        int kc    = b & 15;
        const float* Wih = set ? Wih_dn : Wih_up;
        const float* Whh = set ? Whh_dn : Whh_up;
        unsigned char* img = g_Wb + ((size_t)((set * 32 + chunk) * 16 + kc)) * BLOB_B;
        for (int e = threadIdx.x; e < 192 * 64; e += blockDim.x) {
            int n = e >> 6, col = e & 63;
            int g = n >> 5, jj = n & 31;
            const float* W = (g < 3) ? Wih : Whh;
            int gg = (g < 3) ? g : (g - 3);
            float v = W[(size_t)(gg * HID + chunk * 32 + jj) * HID + kc * 64 + col];
            *(__half*)(img + sw128((uint32_t)(n * 128 + col * 2))) = __float2half_rn(v);
        }
    } else {
        int bb = b - 1024;               // 0..63 = s*16 + kc
        int s = bb >> 4, kc = bb & 15;
        unsigned char* img = g_A0 + (size_t)(s * 16 + kc) * BLOB_A;
        for (int e = threadIdx.x; e < 128 * 64; e += blockDim.x) {
            int m = e >> 6, col = e & 63;
            int gc = kc * 64 + col;
            float v = x[m * EMB + (gc & (EMB - 1))];
            if ((s & 1) && gc >= EMB) v = -v;
            __half hi = __float2half_rn(v);
            __half lo = __float2half_rn(v - __half2float(hi));
            uint32_t sw = sw128((uint32_t)(m * 128 + col * 2));
            *(__half*)(img + sw)         = hi;
            *(__half*)(img + IMG_A + sw) = lo;
        }
    }
}

// ---------------- persistent HMMA GRU kernel ----------------
__global__ __launch_bounds__(THREADS, 1)
void gru_mma_kernel(const float* __restrict__ bih_up, const float* __restrict__ bhh_up,
                    const float* __restrict__ bih_dn, const float* __restrict__ bhh_dn,
                    float* __restrict__ out) {
    extern __shared__ __align__(16) unsigned char dynsmem[];
    __shared__ __align__(8) unsigned long long s_mbar[2 * NSTAGE];  // full[3], emp[3]

    const int tid  = threadIdx.x;
    const int lane = tid & 31;
    const int wid  = tid >> 5;
    const int wm   = wid >> 2;         // 0..1  (M half)
    const int wn   = wid & 3;          // 0..3  (j-oct)

    const int s     = blockIdx.x >> 5;
    const int chunk = blockIdx.x & 31;
    const int wset  = s >> 1;
    const int c0    = chunk * 32;

    const float* bih = wset ? bih_dn : bih_up;
    const float* bhh = wset ? bhh_dn : bhh_up;

    const int j0  = wn * 8 + 2 * (lane & 3);
    const int jg  = c0 + j0;
    const float bR0 = bih[jg]     + bhh[jg];
    const float bR1 = bih[jg + 1] + bhh[jg + 1];
    const float bZ0 = bih[HID + jg]     + bhh[HID + jg];
    const float bZ1 = bih[HID + jg + 1] + bhh[HID + jg + 1];
    const float bI0 = bih[2 * HID + jg],     bI1 = bih[2 * HID + jg + 1];
    const float bH0 = bhh[2 * HID + jg],     bH1 = bhh[2 * HID + jg + 1];

    const uint32_t mb = smem_u32(s_mbar);
    uint32_t mb_full[NSTAGE], mb_emp[NSTAGE];
#pragma unroll
    for (int i = 0; i < NSTAGE; i++) { mb_full[i] = mb + 8 * i; mb_emp[i] = mb + 8 * (NSTAGE + i); }
    if (tid == 0) {
#pragma unroll
        for (int i = 0; i < NSTAGE; i++) {
            mbar_init(mb_full[i], 2);          // one arrive from B-push, one from A-push
            mbar_init(mb_emp[i], THREADS);
        }
    }
    __syncthreads();

    const uint32_t sm0 = (smem_u32(dynsmem) + 1023u) & ~1023u;

    // A ldmatrix addressing (identical to the R4 layout that passed)
    const int rowA  = wm * 64 + (lane & 15);
    const uint32_t axor = (uint32_t)((rowA & 7) << 4);
    const uint32_t aklane = (uint32_t)((lane >> 4) * 16);
    uint32_t arow[4];
#pragma unroll
    for (int mt = 0; mt < 4; mt++) arow[mt] = (uint32_t)((rowA + mt * 16) * 128);

    // B ldmatrix: gate-pair packed x4. Lanes 0-15 -> gate 2p, lanes 16-31 -> gate 2p+1.
    const int rowB2 = wn * 8 + (lane & 7) + ((lane >> 4) & 1) * 32;
    const uint32_t bxor = (uint32_t)((lane & 7) << 4);
    const uint32_t bklane = (uint32_t)(((lane >> 3) & 1) * 16);
    uint32_t brow[3];
#pragma unroll
    for (int p = 0; p < 3; p++) brow[p] = (uint32_t)((rowB2 + p * 64) * 128);

    const unsigned char* Wblob = g_Wb + (size_t)(wset * 32 + chunk) * 16 * BLOB_B;

    float h[16];
#pragma unroll
    for (int i = 0; i < 16; i++) h[i] = 0.0f;

    // producer helpers (tid 0 only)
    auto wait_emp = [&](int q) {
        if (q >= NSTAGE) mbar_wait(mb_emp[q % NSTAGE], (uint32_t)(((q - NSTAGE) / NSTAGE) & 1));
    };
    auto push_B = [&](int q, int kc) {
        wait_emp(q);
        int st = q % NSTAGE;
        mbar_arrive_expect_tx(mb_full[st], BLOB_B);
        bulk_copy(sm0 + (uint32_t)st * STAGE + BLOB_A, Wblob + (size_t)kc * BLOB_B, BLOB_B, mb_full[st]);
    };
    auto push_A = [&](int q, const unsigned char* Ab, int kc) {
        int st = q % NSTAGE;
        mbar_arrive_expect_tx(mb_full[st], BLOB_A);
        bulk_copy(sm0 + (uint32_t)st * STAGE, Ab + (size_t)kc * BLOB_A, BLOB_A, mb_full[st]);
    };

    for (int t = 0; t < SEQLEN; ++t) {
        const unsigned char* Ab = (t == 0)
            ? (g_A0 + (size_t)s * 16 * BLOB_A)
            : (g_St + (size_t)((t & 1) * 4 + s) * 16 * BLOB_A);

        if (tid == 0) {
            if (t == 0) {
#pragma unroll
                for (int i = 0; i < NSTAGE; i++) { push_B(i, i); push_A(i, Ab, i); }
            } else {
                // B for these slots was pushed during the previous step; only A waits for the barrier
#pragma unroll
                for (int i = 0; i < NSTAGE; i++) push_A(t * NKCH + i, Ab, i);
            }
        }

        float acc[4][6][4];
#pragma unroll
        for (int mt = 0; mt < 4; mt++)
#pragma unroll
            for (int g = 0; g < 6; g++)
#pragma unroll
                for (int r = 0; r < 4; r++) acc[mt][g][r] = 0.0f;

        for (int kc = 0; kc < NKCH; ++kc) {
            const int q = t * NKCH + kc;
            const int st = q % NSTAGE;
            mbar_wait(mb_full[st], (uint32_t)((q / NSTAGE) & 1));
            const uint32_t sb  = sm0 + (uint32_t)st * STAGE;
            const uint32_t sAh = sb;
            const uint32_t sAl = sb + IMG_A;
            const uint32_t sBh = sb + BLOB_A;

#pragma unroll
            for (int kk = 0; kk < 4; ++kk) {
                const uint32_t ak = ((uint32_t)(kk * 32) + aklane) ^ axor;
                const uint32_t bk = ((uint32_t)(kk * 32) + bklane) ^ bxor;
                uint32_t ah[4][4], al[4][4], bfr[3][4];
#pragma unroll
                for (int mt = 0; mt < 4; mt++) {
                    ldsm4(ah[mt], sAh + arow[mt] + ak);
                    ldsm4(al[mt], sAl + arow[mt] + ak);
                }
#pragma unroll
                for (int p = 0; p < 3; p++) ldsm4(bfr[p], sBh + brow[p] + bk);

#pragma unroll
                for (int p = 0; p < 3; p++)
#pragma unroll
                    for (int gp = 0; gp < 2; gp++) {
                        const int g = 2 * p + gp;
                        const uint32_t* bf = &bfr[p][2 * gp];
#pragma unroll
                        for (int mt = 0; mt < 4; mt++) {
                            mma16816(acc[mt][g], ah[mt], bf);
                            mma16816(acc[mt][g], al[mt], bf);
                        }
                    }
            }
            mbar_arrive(mb_emp[st]);

            // producer: keep the 3-deep ring full; B crosses the step boundary
            if (tid == 0) {
                int qn = q + NSTAGE;
                if (kc + NSTAGE < NKCH) {
                    push_B(qn, kc + NSTAGE);
                    push_A(qn, Ab, kc + NSTAGE);
                } else if (t + 1 < SEQLEN) {
                    push_B(qn, (kc + NSTAGE) & (NKCH - 1));   // next step, same weights
                }
            }
        }

        // ---------------- epilogue: lane-local gate fusion ----------------
        unsigned char* Sbase = g_St + ((size_t)(((t + 1) & 1) * 4 + s) * 16 + (chunk >> 1)) * BLOB_A;
        const uint32_t colbyte = (uint32_t)(((chunk & 1) * 32 + j0) * 2);

#pragma unroll
        for (int mt = 0; mt < 4; mt++) {
#pragma unroll
            for (int rr = 0; rr < 2; rr++) {
                const int ri = rr * 2;
                const int m  = wm * 64 + mt * 16 + rr * 8 + (lane >> 2);
                float hr0 = 0.f, hz0 = 0.f, hn0 = 0.f, hr1 = 0.f, hz1 = 0.f, hn1 = 0.f;
                if (t) {
                    hr0 = acc[mt][3][ri];     hr1 = acc[mt][3][ri + 1];
                    hz0 = acc[mt][4][ri];     hz1 = acc[mt][4][ri + 1];
                    hn0 = acc[mt][5][ri];     hn1 = acc[mt][5][ri + 1];
                }
                float r0 = sigm(acc[mt][0][ri]     + hr0 + bR0);
                float r1 = sigm(acc[mt][0][ri + 1] + hr1 + bR1);
                float z0 = sigm(acc[mt][1][ri]     + hz0 + bZ0);
                float z1 = sigm(acc[mt][1][ri + 1] + hz1 + bZ1);
                float n0 = tanhf(acc[mt][2][ri]     + bI0 + r0 * (hn0 + bH0));
                float n1 = tanhf(acc[mt][2][ri + 1] + bI1 + r1 * (hn1 + bH1));
                const int idx = mt * 4 + rr * 2;
                float v0 = (1.0f - z0) * n0 + z0 * h[idx];
                float v1 = (1.0f - z1) * n1 + z1 * h[idx + 1];
                h[idx] = v0; h[idx + 1] = v1;

                *reinterpret_cast<float2*>(
                    out + ((size_t)(s * BATCH + m) * SEQLEN + t) * HID + jg) = make_float2(v0, v1);

                __half h0 = __float2half_rn(v0);
                __half h1 = __float2half_rn(v1);
                uint32_t hip = (uint32_t)us16(h0) | ((uint32_t)us16(h1) << 16);
                __half l0 = __float2half_rn(v0 - __half2float(h0));
                __half l1 = __float2half_rn(v1 - __half2float(h1));
                uint32_t lop = (uint32_t)us16(l0) | ((uint32_t)us16(l1) << 16);
                uint32_t sw = sw128((uint32_t)(m * 128) + colbyte);
                *reinterpret_cast<uint32_t*>(Sbase + sw)         = hip;
                *reinterpret_cast<uint32_t*>(Sbase + IMG_A + sw) = lop;
            }
        }
        grid_barrier();
    }
}

extern "C" void kernel_launch(void* const* d_in, const int* in_sizes, int n_in,
                              void* d_out, int out_size) {
    const float* x      = (const float*)d_in[0];
    const float* Wih_up = (const float*)d_in[1];
    const float* Whh_up = (const float*)d_in[2];
    const float* Wih_dn = (const float*)d_in[3];
    const float* Whh_dn = (const float*)d_in[4];
    const float* bih_up = (const float*)d_in[5];
    const float* bhh_up = (const float*)d_in[6];
    const float* bih_dn = (const float*)d_in[7];
    const float* bhh_dn = (const float*)d_in[8];
    float* out = (float*)d_out;

    cudaFuncSetAttribute(gru_mma_kernel, cudaFuncAttributeMaxDynamicSharedMemorySize, DYNSMEM);

    prep_all<<<1088, 256>>>(Wih_up, Whh_up, Wih_dn, Whh_dn, x);
    gru_mma_kernel<<<NCTA, THREADS, DYNSMEM>>>(bih_up, bhh_up, bih_dn, bhh_dn, out);
}

// round 6
// speedup vs baseline: 7.3621x; 1.6441x over previous
#include <cuda_runtime.h>
#include <cuda_fp16.h>
#include <cstdint>

// ---------------- problem constants ----------------
#define NSEQ    4
#define BATCH   128
#define HID     1024
#define EMB     512
#define SEQLEN  256
#define NCTA    128
#define THREADS 256
#define NKCH    16                 // K chunks of 64 per step

#define IMG_A   16384              // 128 rows x 128B (64 fp16), SW128-swizzled
#define BLOB_A  IMG_A              // A hi only = 16KB
#define IMG_B   24576              // 192 rows x 128B
#define BLOB_B  IMG_B              // B hi only = 24KB
#define STAGE   (BLOB_A + BLOB_B)  // 40KB
#define NSTAGE  4
#define DYNSMEM (NSTAGE*STAGE + 1024)

// ---------------- persistent device buffers ----------------
__device__ __align__(16) unsigned char g_Wb[(size_t)2*32*16*BLOB_B]; // 25MB fp16 weights (swizzled)
__device__ __align__(16) unsigned char g_A0[(size_t)4*16*BLOB_A];    // x_spin images
__device__ __align__(16) unsigned char g_St[(size_t)2*4*16*BLOB_A];  // double-buffered h images
__device__ unsigned g_bar_cnt;
__device__ unsigned g_bar_gen;

// ---------------- PTX helpers ----------------
__device__ __forceinline__ uint32_t smem_u32(const void* p) {
    uint32_t a;
    asm("{ .reg .u64 t; cvta.to.shared.u64 t, %1; cvt.u32.u64 %0, t; }" : "=r"(a) : "l"(p));
    return a;
}
__device__ __forceinline__ void mbar_init(uint32_t m, uint32_t cnt) {
    asm volatile("mbarrier.init.shared.b64 [%0], %1;" :: "r"(m), "r"(cnt) : "memory");
}
__device__ __forceinline__ void mbar_arrive_expect_tx(uint32_t m, uint32_t bytes) {
    asm volatile("mbarrier.arrive.expect_tx.shared.b64 _, [%0], %1;" :: "r"(m), "r"(bytes) : "memory");
}
__device__ __forceinline__ void mbar_arrive(uint32_t m) {
    asm volatile("mbarrier.arrive.shared.b64 _, [%0];" :: "r"(m) : "memory");
}
__device__ __forceinline__ void mbar_wait(uint32_t m, uint32_t parity) {
    asm volatile(
        "{\n\t.reg .pred P;\n\t"
        "W_%=:\n\t"
        "mbarrier.try_wait.parity.shared::cta.b64 P, [%0], %1, 0x989680;\n\t"
        "@P bra.uni D_%=;\n\t"
        "bra.uni W_%=;\n\t"
        "D_%=:\n\t}"
        :: "r"(m), "r"(parity) : "memory");
}
__device__ __forceinline__ void bulk_copy(uint32_t dst, const void* src, uint32_t bytes, uint32_t m) {
    asm volatile(
        "cp.async.bulk.shared::cluster.global.mbarrier::complete_tx::bytes [%0], [%1], %2, [%3];"
        :: "r"(dst), "l"(src), "r"(bytes), "r"(m) : "memory");
}
__device__ __forceinline__ void ldsm4(uint32_t* r, uint32_t a) {
    asm volatile("ldmatrix.sync.aligned.m8n8.x4.shared.b16 {%0,%1,%2,%3}, [%4];"
                 : "=r"(r[0]), "=r"(r[1]), "=r"(r[2]), "=r"(r[3]) : "r"(a));
}
__device__ __forceinline__ void mma16816(float* d, const uint32_t* a, const uint32_t* b) {
    asm("mma.sync.aligned.m16n8k16.row.col.f32.f16.f16.f32 "
        "{%0,%1,%2,%3}, {%4,%5,%6,%7}, {%8,%9}, {%0,%1,%2,%3};"
        : "+f"(d[0]), "+f"(d[1]), "+f"(d[2]), "+f"(d[3])
        : "r"(a[0]), "r"(a[1]), "r"(a[2]), "r"(a[3]), "r"(b[0]), "r"(b[1]));
}

__device__ __forceinline__ void grid_barrier() {
    __threadfence();
    __syncthreads();
    if (threadIdx.x == 0) {
        asm volatile("fence.proxy.async.global;" ::: "memory");
        unsigned gen = *((volatile unsigned *)&g_bar_gen);
        __threadfence();
        unsigned my = atomicAdd(&g_bar_cnt, 1);
        if (my == NCTA - 1) {
            atomicExch(&g_bar_cnt, 0);
            __threadfence();
            atomicAdd(&g_bar_gen, 1);
        } else {
            while (*((volatile unsigned *)&g_bar_gen) == gen) { }
        }
        __threadfence();
        asm volatile("fence.proxy.async.global;" ::: "memory");
    }
    __syncthreads();
}

__device__ __forceinline__ float sigm(float x) { return 1.0f / (1.0f + __expf(-x)); }
__device__ __forceinline__ unsigned short us16(__half v) {
    return reinterpret_cast<unsigned short&>(v);
}
__device__ __forceinline__ uint32_t sw128(uint32_t off) { return off ^ ((off >> 3) & 0x70); }

// ---------------- fused prologue: weights + x images (all fp16, swizzled) ----
__global__ void prep_all(const float* __restrict__ Wih_up, const float* __restrict__ Whh_up,
                         const float* __restrict__ Wih_dn, const float* __restrict__ Whh_dn,
                         const float* __restrict__ x) {
    int b = blockIdx.x;
    if (b < 1024) {
        int set   = b >> 9;
        int chunk = (b >> 4) & 31;
        int kc    = b & 15;
        const float* Wih = set ? Wih_dn : Wih_up;
        const float* Whh = set ? Whh_dn : Whh_up;
        unsigned char* img = g_Wb + ((size_t)((set * 32 + chunk) * 16 + kc)) * BLOB_B;
        for (int e = threadIdx.x; e < 192 * 64; e += blockDim.x) {
            int n = e >> 6, col = e & 63;
            int g = n >> 5, jj = n & 31;
            const float* W = (g < 3) ? Wih : Whh;
            int gg = (g < 3) ? g : (g - 3);
            float v = W[(size_t)(gg * HID + chunk * 32 + jj) * HID + kc * 64 + col];
            *(__half*)(img + sw128((uint32_t)(n * 128 + col * 2))) = __float2half_rn(v);
        }
    } else {
        int bb = b - 1024;               // 0..63 = s*16 + kc
        int s = bb >> 4, kc = bb & 15;
        unsigned char* img = g_A0 + (size_t)(s * 16 + kc) * BLOB_A;
        for (int e = threadIdx.x; e < 128 * 64; e += blockDim.x) {
            int m = e >> 6, col = e & 63;
            int gc = kc * 64 + col;
            float v = x[m * EMB + (gc & (EMB - 1))];
            if ((s & 1) && gc >= EMB) v = -v;
            *(__half*)(img + sw128((uint32_t)(m * 128 + col * 2))) = __float2half_rn(v);
        }
    }
}

// ---------------- persistent HMMA GRU kernel ----------------
__global__ __launch_bounds__(THREADS, 1)
void gru_mma_kernel(const float* __restrict__ bih_up, const float* __restrict__ bhh_up,
                    const float* __restrict__ bih_dn, const float* __restrict__ bhh_dn,
                    float* __restrict__ out) {
    extern __shared__ __align__(16) unsigned char dynsmem[];
    __shared__ __align__(8) unsigned long long s_mbar[2 * NSTAGE];  // full[4], emp[4]

    const int tid  = threadIdx.x;
    const int lane = tid & 31;
    const int wid  = tid >> 5;
    const int wm   = wid >> 2;         // 0..1  (M half)
    const int wn   = wid & 3;          // 0..3  (j-oct)

    const int s     = blockIdx.x >> 5;
    const int chunk = blockIdx.x & 31;
    const int wset  = s >> 1;
    const int c0    = chunk * 32;

    const float* bih = wset ? bih_dn : bih_up;
    const float* bhh = wset ? bhh_dn : bhh_up;

    const int j0  = wn * 8 + 2 * (lane & 3);
    const int jg  = c0 + j0;
    const float bR0 = bih[jg]     + bhh[jg];
    const float bR1 = bih[jg + 1] + bhh[jg + 1];
    const float bZ0 = bih[HID + jg]     + bhh[HID + jg];
    const float bZ1 = bih[HID + jg + 1] + bhh[HID + jg + 1];
    const float bI0 = bih[2 * HID + jg],     bI1 = bih[2 * HID + jg + 1];
    const float bH0 = bhh[2 * HID + jg],     bH1 = bhh[2 * HID + jg + 1];

    const uint32_t mb = smem_u32(s_mbar);
    uint32_t mb_full[NSTAGE], mb_emp[NSTAGE];
#pragma unroll
    for (int i = 0; i < NSTAGE; i++) { mb_full[i] = mb + 8 * i; mb_emp[i] = mb + 8 * (NSTAGE + i); }
    if (tid == 0) {
#pragma unroll
        for (int i = 0; i < NSTAGE; i++) {
            mbar_init(mb_full[i], 2);          // one arrive from B-push, one from A-push
            mbar_init(mb_emp[i], THREADS);
        }
    }
    __syncthreads();

    const uint32_t sm0 = (smem_u32(dynsmem) + 1023u) & ~1023u;

    // A ldmatrix addressing
    const int rowA  = wm * 64 + (lane & 15);
    const uint32_t axor = (uint32_t)((rowA & 7) << 4);
    const uint32_t aklane = (uint32_t)((lane >> 4) * 16);
    uint32_t arow[4];
#pragma unroll
    for (int mt = 0; mt < 4; mt++) arow[mt] = (uint32_t)((rowA + mt * 16) * 128);

    // B ldmatrix: gate-pair packed x4. Lanes 0-15 -> gate 2p, lanes 16-31 -> gate 2p+1.
    const int rowB2 = wn * 8 + (lane & 7) + ((lane >> 4) & 1) * 32;
    const uint32_t bxor = (uint32_t)((lane & 7) << 4);
    const uint32_t bklane = (uint32_t)(((lane >> 3) & 1) * 16);
    uint32_t brow[3];
#pragma unroll
    for (int p = 0; p < 3; p++) brow[p] = (uint32_t)((rowB2 + p * 64) * 128);

    const unsigned char* Wblob = g_Wb + (size_t)(wset * 32 + chunk) * 16 * BLOB_B;

    float h[16];
#pragma unroll
    for (int i = 0; i < 16; i++) h[i] = 0.0f;

    // producer helpers (tid 0 only)
    auto wait_emp = [&](int q) {
        if (q >= NSTAGE) mbar_wait(mb_emp[q % NSTAGE], (uint32_t)(((q - NSTAGE) / NSTAGE) & 1));
    };
    auto push_B = [&](int q, int kc) {
        wait_emp(q);
        int st = q % NSTAGE;
        mbar_arrive_expect_tx(mb_full[st], BLOB_B);
        bulk_copy(sm0 + (uint32_t)st * STAGE + BLOB_A, Wblob + (size_t)kc * BLOB_B, BLOB_B, mb_full[st]);
    };
    auto push_A = [&](int q, const unsigned char* Ab, int kc) {
        int st = q % NSTAGE;
        mbar_arrive_expect_tx(mb_full[st], BLOB_A);
        bulk_copy(sm0 + (uint32_t)st * STAGE, Ab + (size_t)kc * BLOB_A, BLOB_A, mb_full[st]);
    };

    for (int t = 0; t < SEQLEN; ++t) {
        const unsigned char* Ab = (t == 0)
            ? (g_A0 + (size_t)s * 16 * BLOB_A)
            : (g_St + (size_t)((t & 1) * 4 + s) * 16 * BLOB_A);

        if (tid == 0) {
            if (t == 0) {
#pragma unroll
                for (int i = 0; i < NSTAGE; i++) { push_B(i, i); push_A(i, Ab, i); }
            } else {
                // B for these slots was pushed during the previous step; only A waits for the barrier
#pragma unroll
                for (int i = 0; i < NSTAGE; i++) push_A(t * NKCH + i, Ab, i);
            }
        }

        float acc[4][6][4];
#pragma unroll
        for (int mt = 0; mt < 4; mt++)
#pragma unroll
            for (int g = 0; g < 6; g++)
#pragma unroll
                for (int r = 0; r < 4; r++) acc[mt][g][r] = 0.0f;

        for (int kc = 0; kc < NKCH; ++kc) {
            const int q = t * NKCH + kc;
            const int st = q % NSTAGE;
            mbar_wait(mb_full[st], (uint32_t)((q / NSTAGE) & 1));
            const uint32_t sb  = sm0 + (uint32_t)st * STAGE;
            const uint32_t sAh = sb;
            const uint32_t sBh = sb + BLOB_A;

#pragma unroll
            for (int kk = 0; kk < 4; ++kk) {
                const uint32_t ak = ((uint32_t)(kk * 32) + aklane) ^ axor;
                const uint32_t bk = ((uint32_t)(kk * 32) + bklane) ^ bxor;
                uint32_t ah[4][4], bfr[3][4];
#pragma unroll
                for (int mt = 0; mt < 4; mt++) ldsm4(ah[mt], sAh + arow[mt] + ak);
#pragma unroll
                for (int p = 0; p < 3; p++) ldsm4(bfr[p], sBh + brow[p] + bk);

#pragma unroll
                for (int p = 0; p < 3; p++)
#pragma unroll
                    for (int gp = 0; gp < 2; gp++) {
                        const int g = 2 * p + gp;
                        const uint32_t* bf = &bfr[p][2 * gp];
#pragma unroll
                        for (int mt = 0; mt < 4; mt++)
                            mma16816(acc[mt][g], ah[mt], bf);
                    }
            }
            mbar_arrive(mb_emp[st]);

            // producer: keep the ring full; B crosses the step boundary
            if (tid == 0) {
                int qn = q + NSTAGE;
                if (kc + NSTAGE < NKCH) {
                    push_B(qn, kc + NSTAGE);
                    push_A(qn, Ab, kc + NSTAGE);
                } else if (t + 1 < SEQLEN) {
                    push_B(qn, (kc + NSTAGE) & (NKCH - 1));   // next step, same weights
                }
            }
        }

        // ---------------- epilogue: lane-local gate fusion ----------------
        unsigned char* Sbase = g_St + ((size_t)(((t + 1) & 1) * 4 + s) * 16 + (chunk >> 1)) * BLOB_A;
        const uint32_t colbyte = (uint32_t)(((chunk & 1) * 32 + j0) * 2);

#pragma unroll
        for (int mt = 0; mt < 4; mt++) {
#pragma unroll
            for (int rr = 0; rr < 2; rr++) {
                const int ri = rr * 2;
                const int m  = wm * 64 + mt * 16 + rr * 8 + (lane >> 2);
                float hr0 = 0.f, hz0 = 0.f, hn0 = 0.f, hr1 = 0.f, hz1 = 0.f, hn1 = 0.f;
                if (t) {
                    hr0 = acc[mt][3][ri];     hr1 = acc[mt][3][ri + 1];
                    hz0 = acc[mt][4][ri];     hz1 = acc[mt][4][ri + 1];
                    hn0 = acc[mt][5][ri];     hn1 = acc[mt][5][ri + 1];
                }
                float r0 = sigm(acc[mt][0][ri]     + hr0 + bR0);
                float r1 = sigm(acc[mt][0][ri + 1] + hr1 + bR1);
                float z0 = sigm(acc[mt][1][ri]     + hz0 + bZ0);
                float z1 = sigm(acc[mt][1][ri + 1] + hz1 + bZ1);
                float n0 = tanhf(acc[mt][2][ri]     + bI0 + r0 * (hn0 + bH0));
                float n1 = tanhf(acc[mt][2][ri + 1] + bI1 + r1 * (hn1 + bH1));
                const int idx = mt * 4 + rr * 2;
                float v0 = (1.0f - z0) * n0 + z0 * h[idx];
                float v1 = (1.0f - z1) * n1 + z1 * h[idx + 1];
                h[idx] = v0; h[idx + 1] = v1;

                *reinterpret_cast<float2*>(
                    out + ((size_t)(s * BATCH + m) * SEQLEN + t) * HID + jg) = make_float2(v0, v1);

                __half h0 = __float2half_rn(v0);
                __half h1 = __float2half_rn(v1);
                uint32_t hip = (uint32_t)us16(h0) | ((uint32_t)us16(h1) << 16);
                uint32_t sw = sw128((uint32_t)(m * 128) + colbyte);
                *reinterpret_cast<uint32_t*>(Sbase + sw) = hip;
            }
        }
        grid_barrier();
    }
}

extern "C" void kernel_launch(void* const* d_in, const int* in_sizes, int n_in,
                              void* d_out, int out_size) {
    const float* x      = (const float*)d_in[0];
    const float* Wih_up = (const float*)d_in[1];
    const float* Whh_up = (const float*)d_in[2];
    const float* Wih_dn = (const float*)d_in[3];
    const float* Whh_dn = (const float*)d_in[4];
    const float* bih_up = (const float*)d_in[5];
    const float* bhh_up = (const float*)d_in[6];
    const float* bih_dn = (const float*)d_in[7];
    const float* bhh_dn = (const float*)d_in[8];
    float* out = (float*)d_out;

    cudaFuncSetAttribute(gru_mma_kernel, cudaFuncAttributeMaxDynamicSharedMemorySize, DYNSMEM);

    prep_all<<<1088, 256>>>(Wih_up, Whh_up, Wih_dn, Whh_dn, x);
    gru_mma_kernel<<<NCTA, THREADS, DYNSMEM>>>(bih_up, bhh_up, bih_dn, bhh_dn, out);
}

// round 7
// speedup vs baseline: 7.6085x; 1.0335x over previous
#include <cuda_runtime.h>
#include <cuda_fp16.h>
#include <cstdint>

// ---------------- problem constants ----------------
#define NSEQ    4
#define BATCH   128
#define HID     1024
#define EMB     512
#define SEQLEN  256
#define NCTA    128
#define THREADS 256
#define NKCH    16                 // K chunks of 64 per step

#define IMG_A   16384              // 128 rows x 128B (64 fp16), SW128-swizzled
#define BLOB_A  IMG_A              // A hi only = 16KB
#define IMG_B   24576              // 192 rows x 128B
#define BLOB_B  IMG_B              // B hi only = 24KB
#define STAGE   (BLOB_A + BLOB_B)  // 40KB
#define NSTAGE  4
#define DYNSMEM (NSTAGE*STAGE + 1024)

#define NFLAG   ((SEQLEN + 1) * NSEQ * NKCH)

// ---------------- persistent device buffers ----------------
__device__ __align__(16) unsigned char g_Wb[(size_t)2*32*16*BLOB_B]; // 25MB fp16 weights (swizzled)
__device__ __align__(16) unsigned char g_A0[(size_t)4*16*BLOB_A];    // x_spin images
__device__ __align__(16) unsigned char g_St[(size_t)2*4*16*BLOB_A];  // double-buffered h images
__device__ unsigned g_flag[NFLAG];                                   // per (t, s, A-chunk) ready counters

// ---------------- PTX helpers ----------------
__device__ __forceinline__ uint32_t smem_u32(const void* p) {
    uint32_t a;
    asm("{ .reg .u64 t; cvta.to.shared.u64 t, %1; cvt.u32.u64 %0, t; }" : "=r"(a) : "l"(p));
    return a;
}
__device__ __forceinline__ void mbar_init(uint32_t m, uint32_t cnt) {
    asm volatile("mbarrier.init.shared.b64 [%0], %1;" :: "r"(m), "r"(cnt) : "memory");
}
__device__ __forceinline__ void mbar_arrive_expect_tx(uint32_t m, uint32_t bytes) {
    asm volatile("mbarrier.arrive.expect_tx.shared.b64 _, [%0], %1;" :: "r"(m), "r"(bytes) : "memory");
}
__device__ __forceinline__ void mbar_arrive(uint32_t m) {
    asm volatile("mbarrier.arrive.shared.b64 _, [%0];" :: "r"(m) : "memory");
}
__device__ __forceinline__ void mbar_wait(uint32_t m, uint32_t parity) {
    asm volatile(
        "{\n\t.reg .pred P;\n\t"
        "W_%=:\n\t"
        "mbarrier.try_wait.parity.shared::cta.b64 P, [%0], %1, 0x989680;\n\t"
        "@P bra.uni D_%=;\n\t"
        "bra.uni W_%=;\n\t"
        "D_%=:\n\t}"
        :: "r"(m), "r"(parity) : "memory");
}
__device__ __forceinline__ void bulk_copy(uint32_t dst, const void* src, uint32_t bytes, uint32_t m) {
    asm volatile(
        "cp.async.bulk.shared::cluster.global.mbarrier::complete_tx::bytes [%0], [%1], %2, [%3];"
        :: "r"(dst), "l"(src), "r"(bytes), "r"(m) : "memory");
}
__device__ __forceinline__ void ldsm4(uint32_t* r, uint32_t a) {
    asm volatile("ldmatrix.sync.aligned.m8n8.x4.shared.b16 {%0,%1,%2,%3}, [%4];"
                 : "=r"(r[0]), "=r"(r[1]), "=r"(r[2]), "=r"(r[3]) : "r"(a));
}
__device__ __forceinline__ void mma16816(float* d, const uint32_t* a, const uint32_t* b) {
    asm("mma.sync.aligned.m16n8k16.row.col.f32.f16.f16.f32 "
        "{%0,%1,%2,%3}, {%4,%5,%6,%7}, {%8,%9}, {%0,%1,%2,%3};"
        : "+f"(d[0]), "+f"(d[1]), "+f"(d[2]), "+f"(d[3])
        : "r"(a[0]), "r"(a[1]), "r"(a[2]), "r"(a[3]), "r"(b[0]), "r"(b[1]));
}

__device__ __forceinline__ float sigm(float x) { return 1.0f / (1.0f + __expf(-x)); }
__device__ __forceinline__ unsigned short us16(__half v) {
    return reinterpret_cast<unsigned short&>(v);
}
__device__ __forceinline__ uint32_t sw128(uint32_t off) { return off ^ ((off >> 3) & 0x70); }

// ---------------- fused prologue: weights + x images + flag clear ----------------
__global__ void prep_all(const float* __restrict__ Wih_up, const float* __restrict__ Whh_up,
                         const float* __restrict__ Wih_dn, const float* __restrict__ Whh_dn,
                         const float* __restrict__ x) {
    int b = blockIdx.x;
    if (b < 1024) {
        int set   = b >> 9;
        int chunk = (b >> 4) & 31;
        int kc    = b & 15;
        const float* Wih = set ? Wih_dn : Wih_up;
        const float* Whh = set ? Whh_dn : Whh_up;
        unsigned char* img = g_Wb + ((size_t)((set * 32 + chunk) * 16 + kc)) * BLOB_B;
        for (int e = threadIdx.x; e < 192 * 64; e += blockDim.x) {
            int n = e >> 6, col = e & 63;
            int g = n >> 5, jj = n & 31;
            const float* W = (g < 3) ? Wih : Whh;
            int gg = (g < 3) ? g : (g - 3);
            float v = W[(size_t)(gg * HID + chunk * 32 + jj) * HID + kc * 64 + col];
            *(__half*)(img + sw128((uint32_t)(n * 128 + col * 2))) = __float2half_rn(v);
        }
    } else if (b < 1088) {
        int bb = b - 1024;               // 0..63 = s*16 + kc
        int s = bb >> 4, kc = bb & 15;
        unsigned char* img = g_A0 + (size_t)(s * 16 + kc) * BLOB_A;
        for (int e = threadIdx.x; e < 128 * 64; e += blockDim.x) {
            int m = e >> 6, col = e & 63;
            int gc = kc * 64 + col;
            float v = x[m * EMB + (gc & (EMB - 1))];
            if ((s & 1) && gc >= EMB) v = -v;
            *(__half*)(img + sw128((uint32_t)(m * 128 + col * 2))) = __float2half_rn(v);
        }
    } else {
        int idx = (b - 1088) * 256 + threadIdx.x;   // flag clear (graph-replay determinism)
        if (idx < NFLAG) g_flag[idx] = 0;
    }
}

// ---------------- persistent HMMA GRU kernel ----------------
__global__ __launch_bounds__(THREADS, 1)
void gru_mma_kernel(const float* __restrict__ bih_up, const float* __restrict__ bhh_up,
                    const float* __restrict__ bih_dn, const float* __restrict__ bhh_dn,
                    float* __restrict__ out) {
    extern __shared__ __align__(16) unsigned char dynsmem[];
    __shared__ __align__(8) unsigned long long s_mbar[2 * NSTAGE];  // full[4], emp[4]

    const int tid  = threadIdx.x;
    const int lane = tid & 31;
    const int wid  = tid >> 5;
    const int wm   = wid >> 2;         // 0..1  (M half)
    const int wn   = wid & 3;          // 0..3  (j-oct)

    const int s     = blockIdx.x >> 5;
    const int chunk = blockIdx.x & 31;
    const int wset  = s >> 1;
    const int c0    = chunk * 32;

    const float* bih = wset ? bih_dn : bih_up;
    const float* bhh = wset ? bhh_dn : bhh_up;

    const int j0  = wn * 8 + 2 * (lane & 3);
    const int jg  = c0 + j0;
    const float bR0 = bih[jg]     + bhh[jg];
    const float bR1 = bih[jg + 1] + bhh[jg + 1];
    const float bZ0 = bih[HID + jg]     + bhh[HID + jg];
    const float bZ1 = bih[HID + jg + 1] + bhh[HID + jg + 1];
    const float bI0 = bih[2 * HID + jg],     bI1 = bih[2 * HID + jg + 1];
    const float bH0 = bhh[2 * HID + jg],     bH1 = bhh[2 * HID + jg + 1];

    const uint32_t mb = smem_u32(s_mbar);
    uint32_t mb_full[NSTAGE], mb_emp[NSTAGE];
#pragma unroll
    for (int i = 0; i < NSTAGE; i++) { mb_full[i] = mb + 8 * i; mb_emp[i] = mb + 8 * (NSTAGE + i); }
    if (tid == 0) {
#pragma unroll
        for (int i = 0; i < NSTAGE; i++) {
            mbar_init(mb_full[i], 2);          // one arrive from B-push, one from A-push
            mbar_init(mb_emp[i], THREADS);
        }
    }
    __syncthreads();

    const uint32_t sm0 = (smem_u32(dynsmem) + 1023u) & ~1023u;

    // A ldmatrix addressing
    const int rowA  = wm * 64 + (lane & 15);
    const uint32_t axor = (uint32_t)((rowA & 7) << 4);
    const uint32_t aklane = (uint32_t)((lane >> 4) * 16);
    uint32_t arow[4];
#pragma unroll
    for (int mt = 0; mt < 4; mt++) arow[mt] = (uint32_t)((rowA + mt * 16) * 128);

    // B ldmatrix: gate-pair packed x4. Lanes 0-15 -> gate 2p, lanes 16-31 -> gate 2p+1.
    const int rowB2 = wn * 8 + (lane & 7) + ((lane >> 4) & 1) * 32;
    const uint32_t bxor = (uint32_t)((lane & 7) << 4);
    const uint32_t bklane = (uint32_t)(((lane >> 3) & 1) * 16);
    uint32_t brow[3];
#pragma unroll
    for (int p = 0; p < 3; p++) brow[p] = (uint32_t)((rowB2 + p * 64) * 128);

    const unsigned char* Wblob = g_Wb + (size_t)(wset * 32 + chunk) * 16 * BLOB_B;

    float h[16];
#pragma unroll
    for (int i = 0; i < 16; i++) h[i] = 0.0f;

    // producer helpers (tid 0 only)
    auto wait_emp = [&](int q) {
        if (q >= NSTAGE) mbar_wait(mb_emp[q % NSTAGE], (uint32_t)(((q - NSTAGE) / NSTAGE) & 1));
    };
    auto push_B = [&](int q, int kc) {
        wait_emp(q);
        int st = q % NSTAGE;
        mbar_arrive_expect_tx(mb_full[st], BLOB_B);
        bulk_copy(sm0 + (uint32_t)st * STAGE + BLOB_A, Wblob + (size_t)kc * BLOB_B, BLOB_B, mb_full[st]);
    };
    auto push_A = [&](int t, int q, const unsigned char* Ab, int kc) {
        if (t > 0) {   // wait until both producer CTAs of this A chunk finished step t-1
            volatile unsigned* f = &g_flag[(t * NSEQ + s) * NKCH + kc];
            while (*f < 2u) { }
            asm volatile("fence.proxy.async.global;" ::: "memory");
        }
        int st = q % NSTAGE;
        mbar_arrive_expect_tx(mb_full[st], BLOB_A);
        bulk_copy(sm0 + (uint32_t)st * STAGE, Ab + (size_t)kc * BLOB_A, BLOB_A, mb_full[st]);
    };

    for (int t = 0; t < SEQLEN; ++t) {
        const unsigned char* Ab = (t == 0)
            ? (g_A0 + (size_t)s * 16 * BLOB_A)
            : (g_St + (size_t)((t & 1) * 4 + s) * 16 * BLOB_A);

        if (tid == 0) {
            if (t == 0) {
#pragma unroll
                for (int i = 0; i < NSTAGE; i++) { push_B(i, i); push_A(t, i, Ab, i); }
            } else {
                // B for these slots was pushed during the previous step; A polls its 2 producers
#pragma unroll
                for (int i = 0; i < NSTAGE; i++) push_A(t, t * NKCH + i, Ab, i);
            }
        }

        float acc[4][6][4];
#pragma unroll
        for (int mt = 0; mt < 4; mt++)
#pragma unroll
            for (int g = 0; g < 6; g++)
#pragma unroll
                for (int r = 0; r < 4; r++) acc[mt][g][r] = 0.0f;

        for (int kc = 0; kc < NKCH; ++kc) {
            const int q = t * NKCH + kc;
            const int st = q % NSTAGE;
            mbar_wait(mb_full[st], (uint32_t)((q / NSTAGE) & 1));
            const uint32_t sb  = sm0 + (uint32_t)st * STAGE;
            const uint32_t sAh = sb;
            const uint32_t sBh = sb + BLOB_A;

#pragma unroll
            for (int kk = 0; kk < 4; ++kk) {
                const uint32_t ak = ((uint32_t)(kk * 32) + aklane) ^ axor;
                const uint32_t bk = ((uint32_t)(kk * 32) + bklane) ^ bxor;
                uint32_t ah[4][4], bfr[3][4];
#pragma unroll
                for (int mt = 0; mt < 4; mt++) ldsm4(ah[mt], sAh + arow[mt] + ak);
#pragma unroll
                for (int p = 0; p < 3; p++) ldsm4(bfr[p], sBh + brow[p] + bk);

#pragma unroll
                for (int p = 0; p < 3; p++)
#pragma unroll
                    for (int gp = 0; gp < 2; gp++) {
                        const int g = 2 * p + gp;
                        const uint32_t* bf = &bfr[p][2 * gp];
#pragma unroll
                        for (int mt = 0; mt < 4; mt++)
                            mma16816(acc[mt][g], ah[mt], bf);
                    }
            }
            mbar_arrive(mb_emp[st]);

            // producer: keep the ring full; B crosses the step boundary
            if (tid == 0) {
                int qn = q + NSTAGE;
                if (kc + NSTAGE < NKCH) {
                    push_B(qn, kc + NSTAGE);
                    push_A(t, qn, Ab, kc + NSTAGE);
                } else if (t + 1 < SEQLEN) {
                    push_B(qn, (kc + NSTAGE) & (NKCH - 1));   // next step, same weights
                }
            }
        }

        // ---------------- epilogue: lane-local gate fusion ----------------
        unsigned char* Sbase = g_St + ((size_t)(((t + 1) & 1) * 4 + s) * 16 + (chunk >> 1)) * BLOB_A;
        const uint32_t colbyte = (uint32_t)(((chunk & 1) * 32 + j0) * 2);

#pragma unroll
        for (int mt = 0; mt < 4; mt++) {
#pragma unroll
            for (int rr = 0; rr < 2; rr++) {
                const int ri = rr * 2;
                const int m  = wm * 64 + mt * 16 + rr * 8 + (lane >> 2);
                float hr0 = 0.f, hz0 = 0.f, hn0 = 0.f, hr1 = 0.f, hz1 = 0.f, hn1 = 0.f;
                if (t) {
                    hr0 = acc[mt][3][ri];     hr1 = acc[mt][3][ri + 1];
                    hz0 = acc[mt][4][ri];     hz1 = acc[mt][4][ri + 1];
                    hn0 = acc[mt][5][ri];     hn1 = acc[mt][5][ri + 1];
                }
                float r0 = sigm(acc[mt][0][ri]     + hr0 + bR0);
                float r1 = sigm(acc[mt][0][ri + 1] + hr1 + bR1);
                float z0 = sigm(acc[mt][1][ri]     + hz0 + bZ0);
                float z1 = sigm(acc[mt][1][ri + 1] + hz1 + bZ1);
                float n0 = tanhf(acc[mt][2][ri]     + bI0 + r0 * (hn0 + bH0));
                float n1 = tanhf(acc[mt][2][ri + 1] + bI1 + r1 * (hn1 + bH1));
                const int idx = mt * 4 + rr * 2;
                float v0 = (1.0f - z0) * n0 + z0 * h[idx];
                float v1 = (1.0f - z1) * n1 + z1 * h[idx + 1];
                h[idx] = v0; h[idx + 1] = v1;

                *reinterpret_cast<float2*>(
                    out + ((size_t)(s * BATCH + m) * SEQLEN + t) * HID + jg) = make_float2(v0, v1);

                __half h0 = __float2half_rn(v0);
                __half h1 = __float2half_rn(v1);
                uint32_t hip = (uint32_t)us16(h0) | ((uint32_t)us16(h1) << 16);
                uint32_t sw = sw128((uint32_t)(m * 128) + colbyte);
                *reinterpret_cast<uint32_t*>(Sbase + sw) = hip;
            }
        }

        // publish: this CTA's slice of next step's A chunk (chunk>>1) is ready
        __threadfence();
        asm volatile("fence.proxy.async.global;" ::: "memory");
        __syncthreads();
        if (tid == 0 && t + 1 < SEQLEN)
            atomicAdd(&g_flag[((t + 1) * NSEQ + s) * NKCH + (chunk >> 1)], 1u);
    }
}

extern "C" void kernel_launch(void* const* d_in, const int* in_sizes, int n_in,
                              void* d_out, int out_size) {
    const float* x      = (const float*)d_in[0];
    const float* Wih_up = (const float*)d_in[1];
    const float* Whh_up = (const float*)d_in[2];
    const float* Wih_dn = (const float*)d_in[3];
    const float* Whh_dn = (const float*)d_in[4];
    const float* bih_up = (const float*)d_in[5];
    const float* bhh_up = (const float*)d_in[6];
    const float* bih_dn = (const float*)d_in[7];
    const float* bhh_dn = (const float*)d_in[8];
    float* out = (float*)d_out;

    cudaFuncSetAttribute(gru_mma_kernel, cudaFuncAttributeMaxDynamicSharedMemorySize, DYNSMEM);

    // 1024 weight blocks + 64 x-image blocks + 65 flag-clear blocks
    prep_all<<<1153, 256>>>(Wih_up, Whh_up, Wih_dn, Whh_dn, x);
    gru_mma_kernel<<<NCTA, THREADS, DYNSMEM>>>(bih_up, bhh_up, bih_dn, bhh_dn, out);
}